// round 11
// baseline (speedup 1.0000x reference)
#include <cuda_runtime.h>
#include <cfloat>

// Problem constants (reference: xyz [4, 8192, 3], K=16)
#define BB   4
#define NN   8192
#define GG   24
#define NC   (GG * GG * GG)       // 13824
#define NBLK (NC / 256)           // 54 scan blocks per batch
#define KK   16
#define TPB  128                  // 4 warps per search block
#define WPB  4
#define MAXS 176                  // per-warp segment table capacity
#define FULL 0xffffffffu

// ---- device scratch (static: allocation-free) ----
__device__ float4 g_pts[BB][NN];        // cell-sorted points (x,y,z,|x|^2)
__device__ int    g_pidx[BB][NN];       // original indices, cell-sorted
__device__ int    g_cnt[BB][NC];        // per-cell counts
__device__ int    g_cst[BB][NC + 1];    // per-cell start offsets
__device__ int    g_cur[BB][NC];        // scatter cursors
__device__ int    g_bsum[BB][NBLK];     // scan block sums
__device__ int    g_boff[BB][NBLK];     // scan block offsets
__device__ float  g_bb[BB][6];          // minx,miny,minz,maxx,maxy,maxz

__device__ __forceinline__ bool lex_less(float d, int i, float ed, int ei) {
    return (d < ed) || (d == ed && i < ei);
}

// Ascending lexicographic bitonic sort of 32 (d,i) pairs across the warp.
__device__ __forceinline__ void bitonic32(float& d, int& i, int lane) {
#pragma unroll
    for (int k = 2; k <= 32; k <<= 1) {
#pragma unroll
        for (int j = k >> 1; j > 0; j >>= 1) {
            const float od = __shfl_xor_sync(FULL, d, j);
            const int   oi = __shfl_xor_sync(FULL, i, j);
            const bool keep_min = ((lane & k) == 0) == ((lane & j) == 0);
            const bool less = lex_less(od, oi, d, i);
            if (keep_min == less) { d = od; i = oi; }
        }
    }
}

// ---- 1: fused zero-counts + per-batch bbox ----
__global__ __launch_bounds__(256)
void k_pre(const float* __restrict__ xyz) {
    if (blockIdx.x >= BB) {
        const int i = (blockIdx.x - BB) * 256 + threadIdx.x;
        if (i < BB * NC) ((int*)g_cnt)[i] = 0;
        return;
    }
    const int b = blockIdx.x;
    const float* base = xyz + (size_t)b * NN * 3;
    float mn0 = FLT_MAX, mn1 = FLT_MAX, mn2 = FLT_MAX;
    float mx0 = -FLT_MAX, mx1 = -FLT_MAX, mx2 = -FLT_MAX;
    for (int i = threadIdx.x; i < NN; i += 256) {
        const float x = base[3 * i + 0], y = base[3 * i + 1], z = base[3 * i + 2];
        mn0 = fminf(mn0, x); mx0 = fmaxf(mx0, x);
        mn1 = fminf(mn1, y); mx1 = fmaxf(mx1, y);
        mn2 = fminf(mn2, z); mx2 = fmaxf(mx2, z);
    }
#pragma unroll
    for (int o = 16; o; o >>= 1) {
        mn0 = fminf(mn0, __shfl_xor_sync(FULL, mn0, o));
        mn1 = fminf(mn1, __shfl_xor_sync(FULL, mn1, o));
        mn2 = fminf(mn2, __shfl_xor_sync(FULL, mn2, o));
        mx0 = fmaxf(mx0, __shfl_xor_sync(FULL, mx0, o));
        mx1 = fmaxf(mx1, __shfl_xor_sync(FULL, mx1, o));
        mx2 = fmaxf(mx2, __shfl_xor_sync(FULL, mx2, o));
    }
    __shared__ float s[6][8];
    const int w = threadIdx.x >> 5, l = threadIdx.x & 31;
    if (l == 0) {
        s[0][w] = mn0; s[1][w] = mn1; s[2][w] = mn2;
        s[3][w] = mx0; s[4][w] = mx1; s[5][w] = mx2;
    }
    __syncthreads();
    if (threadIdx.x == 0) {
        float a0 = FLT_MAX, a1 = FLT_MAX, a2 = FLT_MAX;
        float b0 = -FLT_MAX, b1 = -FLT_MAX, b2 = -FLT_MAX;
#pragma unroll
        for (int i = 0; i < 8; i++) {
            a0 = fminf(a0, s[0][i]); a1 = fminf(a1, s[1][i]); a2 = fminf(a2, s[2][i]);
            b0 = fmaxf(b0, s[3][i]); b1 = fmaxf(b1, s[4][i]); b2 = fmaxf(b2, s[5][i]);
        }
        g_bb[b][0] = a0 - 1e-4f; g_bb[b][1] = a1 - 1e-4f; g_bb[b][2] = a2 - 1e-4f;
        g_bb[b][3] = b0 + 1e-4f; g_bb[b][4] = b1 + 1e-4f; g_bb[b][5] = b2 + 1e-4f;
    }
}

// Cell assignment — SAME formula everywhere.
__device__ __forceinline__ int cell1(float v, float mn, float inv) {
    int c = (int)((v - mn) * inv);
    return min(GG - 1, max(0, c));
}

// ---- 2: count points per cell ----
__global__ void k_count(const float* __restrict__ xyz) {
    const int gi = blockIdx.x * blockDim.x + threadIdx.x;
    if (gi >= BB * NN) return;
    const int b = gi >> 13, i = gi & (NN - 1);
    const float* base = xyz + (size_t)b * NN * 3;
    const float x = base[3 * i + 0], y = base[3 * i + 1], z = base[3 * i + 2];
    const float mnx = g_bb[b][0], mny = g_bb[b][1], mnz = g_bb[b][2];
    const float ivx = GG / (g_bb[b][3] - mnx);
    const float ivy = GG / (g_bb[b][4] - mny);
    const float ivz = GG / (g_bb[b][5] - mnz);
    const int cx = cell1(x, mnx, ivx), cy = cell1(y, mny, ivy), cz = cell1(z, mnz, ivz);
    atomicAdd(&g_cnt[b][(cz * GG + cy) * GG + cx], 1);
}

// ---- 3a: per-block local scan ----
__global__ __launch_bounds__(256)
void k_scan1() {
    const int blk = blockIdx.x;
    const int b = blk / NBLK, lb = blk - b * NBLK;
    const int cell = lb * 256 + threadIdx.x;
    const int lane = threadIdx.x & 31, wid = threadIdx.x >> 5;

    const int c = g_cnt[b][cell];
    int s = c;
#pragma unroll
    for (int o = 1; o < 32; o <<= 1) {
        const int v = __shfl_up_sync(FULL, s, o);
        if (lane >= o) s += v;
    }
    __shared__ int wsum[8];
    if (lane == 31) wsum[wid] = s;
    __syncthreads();
    if (threadIdx.x < 8) {
        int x = wsum[threadIdx.x];
        int e = x;
#pragma unroll
        for (int o = 1; o < 8; o <<= 1) {
            const int v = __shfl_up_sync(0xffu, e, o);
            if (threadIdx.x >= o) e += v;
        }
        wsum[threadIdx.x] = e - x;
    }
    __syncthreads();
    const int excl = s - c + wsum[wid];
    g_cst[b][cell] = excl;
    if (threadIdx.x == 255) g_bsum[b][lb] = excl + c;
}

// ---- 3b: scan of block sums (1 warp per batch) ----
__global__ void k_scan2() {
    const int b = threadIdx.x >> 5, l = threadIdx.x & 31;
    if (b >= BB) return;
    int v0 = g_bsum[b][l];
    int s0 = v0;
#pragma unroll
    for (int o = 1; o < 32; o <<= 1) {
        const int v = __shfl_up_sync(FULL, s0, o);
        if (l >= o) s0 += v;
    }
    const int t0 = __shfl_sync(FULL, s0, 31);
    const int i1 = 32 + l;
    int v1 = (i1 < NBLK) ? g_bsum[b][i1] : 0;
    int s1 = v1;
#pragma unroll
    for (int o = 1; o < 32; o <<= 1) {
        const int v = __shfl_up_sync(FULL, s1, o);
        if (l >= o) s1 += v;
    }
    s1 += t0;
    g_boff[b][l] = s0 - v0;
    if (i1 < NBLK) g_boff[b][i1] = s1 - v1;
    if (l == 0) g_cst[b][NC] = NN;
}

// ---- 3c: add block offsets, init cursors ----
__global__ __launch_bounds__(256)
void k_scan3() {
    const int blk = blockIdx.x;
    const int b = blk / NBLK, lb = blk - b * NBLK;
    const int cell = lb * 256 + threadIdx.x;
    const int v = g_cst[b][cell] + g_boff[b][lb];
    g_cst[b][cell] = v;
    g_cur[b][cell] = v;
}

// ---- 4: scatter points into cell-sorted order ----
__global__ void k_scatter(const float* __restrict__ xyz) {
    const int gi = blockIdx.x * blockDim.x + threadIdx.x;
    if (gi >= BB * NN) return;
    const int b = gi >> 13, i = gi & (NN - 1);
    const float* base = xyz + (size_t)b * NN * 3;
    const float x = base[3 * i + 0], y = base[3 * i + 1], z = base[3 * i + 2];
    const float mnx = g_bb[b][0], mny = g_bb[b][1], mnz = g_bb[b][2];
    const float ivx = GG / (g_bb[b][3] - mnx);
    const float ivy = GG / (g_bb[b][4] - mny);
    const float ivz = GG / (g_bb[b][5] - mnz);
    const int cx = cell1(x, mnx, ivx), cy = cell1(y, mny, ivy), cz = cell1(z, mnz, ivz);
    const int pos = atomicAdd(&g_cur[b][(cz * GG + cy) * GG + cx], 1);
    g_pts[b][pos] = make_float4(x, y, z, x * x + y * y + z * z);   // frozen R1 form
    g_pidx[b][pos] = i;
}

// ---- 5: pair-per-warp expanding-ring exact kNN (pipelined) ----
__global__ __launch_bounds__(TPB)
void k_search(const float* __restrict__ xyz, float* __restrict__ out, int out_size) {
    __shared__ int s_ps[WPB][MAXS];
    __shared__ int s_pe[WPB][MAXS];

    const int lane = threadIdx.x & 31;
    const int wid  = threadIdx.x >> 5;
    const int gp = blockIdx.x * WPB + wid;    // pair id, 0..BB*NN/2-1
    const int b  = gp >> 12;                  // 4096 pairs per batch
    const int lp = gp & 4095;
    const int sA = 2 * lp, sB = sA + 1;
    const int t   = lane & 15;
    const int seg = lane >> 4;

    const float4 pA = g_pts[b][sA];
    const float4 pB = g_pts[b][sB];
    const int qidA = g_pidx[b][sA];
    const int qidB = g_pidx[b][sB];

    const float mnx = g_bb[b][0], mny = g_bb[b][1], mnz = g_bb[b][2];
    const float ex = g_bb[b][3] - mnx, ey = g_bb[b][4] - mny, ez = g_bb[b][5] - mnz;
    const float ivx = GG / ex, ivy = GG / ey, ivz = GG / ez;
    const float wx = ex * (1.0f / GG), wy = ey * (1.0f / GG), wz = ez * (1.0f / GG);

    const int cxA = cell1(pA.x, mnx, ivx), cyA = cell1(pA.y, mny, ivy), czA = cell1(pA.z, mnz, ivz);
    const int cxB = cell1(pB.x, mnx, ivx), cyB = cell1(pB.y, mny, ivy), czB = cell1(pB.z, mnz, ivz);
    const bool adj = (abs(cxA - cxB) <= 1) && (abs(cyA - cyB) <= 1) && (abs(czA - czB) <= 1);
    const int npass = adj ? 1 : 2;

    const float4* __restrict__ pts  = g_pts[b];
    const int*    __restrict__ pidx = g_pidx[b];
    const int*    __restrict__ cst  = g_cst[b];
    const float*  __restrict__ base = xyz + (size_t)b * NN * 3;

    const size_t feat_total = (size_t)BB * NN * KK * 10;
    const bool write_idx = ((size_t)out_size >= feat_total + (size_t)BB * NN * KK);

    for (int pass = 0; pass < npass; pass++) {
        const float4 P0 = (pass == 0) ? pA : pB;
        const float4 P1 = adj ? pB : P0;
        const float q0x = P0.x, q0y = P0.y, q0z = P0.z, s0 = P0.w;
        const float q1x = P1.x, q1y = P1.y, q1z = P1.z, s1 = P1.w;

        int xlo, xhi, ylo, yhi, zlo, zhi;
        if (adj) {
            xlo = min(cxA, cxB); xhi = max(cxA, cxB);
            ylo = min(cyA, cyB); yhi = max(cyA, cyB);
            zlo = min(czA, czB); zhi = max(czA, czB);
        } else if (pass == 0) {
            xlo = xhi = cxA; ylo = yhi = cyA; zlo = zhi = czA;
        } else {
            xlo = xhi = cxB; ylo = yhi = cyB; zlo = zhi = czB;
        }

        float ld = FLT_MAX;
        int   li = 0x7fffffff;
        float tau0 = FLT_MAX;
        float tau1 = adj ? FLT_MAX : -FLT_MAX;
        bool warm = false;
        bool done = false;

#define ROUND(CC, CI)                                                           \
        {                                                                       \
            float dot0 = q0x * (CC).x;                                          \
            dot0 = fmaf(q0y, (CC).y, dot0);                                     \
            dot0 = fmaf(q0z, (CC).z, dot0);                                     \
            float dot1 = q1x * (CC).x;                                          \
            dot1 = fmaf(q1y, (CC).y, dot1);                                     \
            dot1 = fmaf(q1z, (CC).z, dot1);                                     \
            const float d2a = fmaf(-2.0f, dot0, s0 + (CC).w);                   \
            const float d2b = fmaf(-2.0f, dot1, s1 + (CC).w);                   \
            unsigned m0 = __ballot_sync(FULL, d2a < tau0);                      \
            unsigned m1 = __ballot_sync(FULL, d2b < tau1);                      \
            if (m0 | m1) {                                                      \
                const bool had0 = (m0 != 0), had1 = (m1 != 0);                  \
                while (m0) {                                                    \
                    const int src = __ffs(m0) - 1;                              \
                    m0 &= m0 - 1;                                               \
                    const float dv = __shfl_sync(FULL, d2a, src);               \
                    const int   iv = __shfl_sync(FULL, (CI), src);              \
                    const float pd = __shfl_up_sync(FULL, ld, 1, 16);           \
                    const int   pi2 = __shfl_up_sync(FULL, li, 1, 16);          \
                    const bool ct = lex_less(dv, iv, ld, li);                   \
                    const bool cp = (t > 0) && lex_less(dv, iv, pd, pi2);       \
                    if (seg == 0 && ct) { ld = cp ? pd : dv; li = cp ? pi2 : iv; } \
                }                                                               \
                while (m1) {                                                    \
                    const int src = __ffs(m1) - 1;                              \
                    m1 &= m1 - 1;                                               \
                    const float dv = __shfl_sync(FULL, d2b, src);               \
                    const int   iv = __shfl_sync(FULL, (CI), src);              \
                    const float pd = __shfl_up_sync(FULL, ld, 1, 16);           \
                    const int   pi2 = __shfl_up_sync(FULL, li, 1, 16);          \
                    const bool ct = lex_less(dv, iv, ld, li);                   \
                    const bool cp = (t > 0) && lex_less(dv, iv, pd, pi2);       \
                    if (seg == 1 && ct) { ld = cp ? pd : dv; li = cp ? pi2 : iv; } \
                }                                                               \
                if (had0) tau0 = __shfl_sync(FULL, ld, 15);                     \
                if (had1) tau1 = __shfl_sync(FULL, ld, 15 + 16);                \
            }                                                                   \
        }

#define WARMUP(CC, CI)                                                          \
        {                                                                       \
            float dot0 = q0x * (CC).x;                                          \
            dot0 = fmaf(q0y, (CC).y, dot0);                                     \
            dot0 = fmaf(q0z, (CC).z, dot0);                                     \
            float dot1 = q1x * (CC).x;                                          \
            dot1 = fmaf(q1y, (CC).y, dot1);                                     \
            dot1 = fmaf(q1z, (CC).z, dot1);                                     \
            const float d2a = fmaf(-2.0f, dot0, s0 + (CC).w);                   \
            const float d2b = fmaf(-2.0f, dot1, s1 + (CC).w);                   \
            float da = d2a; int ia = (CI);                                      \
            bitonic32(da, ia, lane);                                            \
            float db = d2b; int ib = (CI);                                      \
            bitonic32(db, ib, lane);                                            \
            const float d1v = __shfl_sync(FULL, db, (lane - 16) & 31);          \
            const int   i1v = __shfl_sync(FULL, ib, (lane - 16) & 31);          \
            ld = seg ? d1v : da;                                                \
            li = seg ? i1v : ia;                                                \
            tau0 = __shfl_sync(FULL, ld, 15);                                   \
            tau1 = adj ? __shfl_sync(FULL, ld, 31) : -FLT_MAX;                  \
        }

        for (int r = 1; r <= GG + 1 && !done; r++) {
            const int Z0 = zlo - r, Z1 = zhi + r;
            const int Y0 = ylo - r, Y1 = yhi + r;
            const int X0 = xlo - r, X1 = xhi + r;
            const int Ny = Y1 - Y0 + 1;
            const int nrow = (Z1 - Z0 + 1) * Ny;

            if (2 * nrow <= MAXS) {
                // ---- Lane-parallel segment table fill ----
                for (int s = lane; s < 2 * nrow; s += 32) {
                    const int row = s >> 1, which = s & 1;
                    const int z = Z0 + row / Ny, y = Y0 + row % Ny;
                    int ps = 0, pe = 0;
                    if (z >= 0 && z < GG && y >= 0 && y < GG) {
                        const int rowb = (z * GG + y) * GG;
                        const bool fullrow = (r == 1) || z == Z0 || z == Z1 || y == Y0 || y == Y1;
                        if (fullrow) {
                            if (which == 0) {
                                const int a = max(X0, 0), bx = min(X1, GG - 1);
                                ps = cst[rowb + a]; pe = cst[rowb + bx + 1];
                            }
                        } else {
                            const int xx = which ? X1 : X0;
                            if (xx >= 0 && xx < GG) {
                                ps = cst[rowb + xx]; pe = cst[rowb + xx + 1];
                            }
                        }
                    }
                    s_ps[wid][s] = ps;
                    s_pe[wid][s] = pe;
                }
                __syncwarp(FULL);

                // ---- Pipelined rounds over the segment stream ----
                const int nsegs = 2 * nrow;
                int cs = 0;
                int cp = s_ps[wid][0], ce = s_pe[wid][0];
                while (cp >= ce && ++cs < nsegs) { cp = s_ps[wid][cs]; ce = s_pe[wid][cs]; }

                int c0 = 0;
                float4 cc;
                int ci = 0x7fffffff;
                bool have = false;
                if (cs < nsegs) {
                    const int b0 = cp;
                    c0 = min(32, ce - cp);
                    cp += c0;
                    const bool ok = lane < c0;
                    cc = ok ? pts[b0 + lane] : make_float4(0.f, 0.f, 0.f, FLT_MAX);
                    ci = ok ? pidx[b0 + lane] : 0x7fffffff;
                    have = true;
                }
                while (have) {
                    // Fetch next round (LDGs fly while current round processes)
                    float4 nc;
                    int ni = 0x7fffffff;
                    bool nhave = false;
                    while (cp >= ce && ++cs < nsegs) { cp = s_ps[wid][cs]; ce = s_pe[wid][cs]; }
                    if (cs < nsegs) {
                        const int b1 = cp;
                        const int c1 = min(32, ce - cp);
                        cp += c1;
                        const bool ok = lane < c1;
                        nc = ok ? pts[b1 + lane] : make_float4(0.f, 0.f, 0.f, FLT_MAX);
                        ni = ok ? pidx[b1 + lane] : 0x7fffffff;
                        nhave = true;
                    }
                    if (!warm) {
                        WARMUP(cc, ci);
                        warm = true;
                    } else {
                        ROUND(cc, ci);
                    }
                    cc = nc; ci = ni; have = nhave;
                }
            } else {
                // ---- Serial fallback for rare large rings (warm is true by now) ----
                for (int z = max(Z0, 0); z <= min(Z1, GG - 1); z++) {
                    for (int y = max(Y0, 0); y <= min(Y1, GG - 1); y++) {
                        const int rowb = (z * GG + y) * GG;
                        const bool fullrow = z == Z0 || z == Z1 || y == Y0 || y == Y1;
                        int segs_x[2]; int nsx = 0;
                        int a0 = 0, a1 = -1;
                        if (fullrow) { a0 = max(X0, 0); a1 = min(X1, GG - 1); }
                        else {
                            if (X0 >= 0) segs_x[nsx++] = X0;
                            if (X1 < GG) segs_x[nsx++] = X1;
                        }
                        if (fullrow) {
                            if (a0 <= a1) {
                                const int ps = cst[rowb + a0], pe = cst[rowb + a1 + 1];
                                for (int p0 = ps; p0 < pe; p0 += 32) {
                                    const int p = p0 + lane;
                                    const bool ok = p < pe;
                                    const float4 c2 = ok ? pts[p] : make_float4(0.f, 0.f, 0.f, FLT_MAX);
                                    const int   i2 = ok ? pidx[p] : 0x7fffffff;
                                    ROUND(c2, i2);
                                }
                            }
                        } else {
                            for (int u = 0; u < nsx; u++) {
                                const int ps = cst[rowb + segs_x[u]], pe = cst[rowb + segs_x[u] + 1];
                                for (int p0 = ps; p0 < pe; p0 += 32) {
                                    const int p = p0 + lane;
                                    const bool ok = p < pe;
                                    const float4 c2 = ok ? pts[p] : make_float4(0.f, 0.f, 0.f, FLT_MAX);
                                    const int   i2 = ok ? pidx[p] : 0x7fffffff;
                                    ROUND(c2, i2);
                                }
                            }
                        }
                    }
                }
            }

            // ---- Per-query exact stop bound from super-block faces ----
            const bool covered = (X0 <= 0) && (X1 >= GG - 1) && (Y0 <= 0) &&
                                 (Y1 >= GG - 1) && (Z0 <= 0) && (Z1 >= GG - 1);
            float b0d = FLT_MAX;
            if (X0 > 0)      b0d = fminf(b0d, q0x - (mnx + X0 * wx));
            if (X1 < GG - 1) b0d = fminf(b0d, (mnx + (X1 + 1) * wx) - q0x);
            if (Y0 > 0)      b0d = fminf(b0d, q0y - (mny + Y0 * wy));
            if (Y1 < GG - 1) b0d = fminf(b0d, (mny + (Y1 + 1) * wy) - q0y);
            if (Z0 > 0)      b0d = fminf(b0d, q0z - (mnz + Z0 * wz));
            if (Z1 < GG - 1) b0d = fminf(b0d, (mnz + (Z1 + 1) * wz) - q0z);
            const bool d0 = (tau0 < FLT_MAX) && (tau0 <= 0.98f * b0d * b0d);
            bool d1 = true;
            if (adj) {
                float b1d = FLT_MAX;
                if (X0 > 0)      b1d = fminf(b1d, q1x - (mnx + X0 * wx));
                if (X1 < GG - 1) b1d = fminf(b1d, (mnx + (X1 + 1) * wx) - q1x);
                if (Y0 > 0)      b1d = fminf(b1d, q1y - (mny + Y0 * wy));
                if (Y1 < GG - 1) b1d = fminf(b1d, (mny + (Y1 + 1) * wy) - q1y);
                if (Z0 > 0)      b1d = fminf(b1d, q1z - (mnz + Z0 * wz));
                if (Z1 < GG - 1) b1d = fminf(b1d, (mnz + (Z1 + 1) * wz) - q1z);
                d1 = (tau1 < FLT_MAX) && (tau1 <= 0.98f * b1d * b1d);
            }
            done = covered || (d0 && d1);
        }
#undef ROUND
#undef WARMUP

        // ---- Epilogue for this pass ----
        const bool writer = adj ? true : (lane < 16);
        if (writer) {
            const int   q  = adj ? (seg ? qidB : qidA) : (pass == 0 ? qidA : qidB);
            const float qx = adj ? (seg ? pB.x : pA.x) : q0x;
            const float qy = adj ? (seg ? pB.y : pA.y) : q0y;
            const float qz = adj ? (seg ? pB.z : pA.z) : q0z;

            const size_t qlin = (size_t)b * NN + q;
            const int j = li;
            const float nx = base[3 * j + 0];
            const float ny = base[3 * j + 1];
            const float nz = base[3 * j + 2];

            float* p = out + qlin * KK * 10 + (size_t)t * 10;
            p[0] = ld;
            p[1] = qx - nx;
            p[2] = qy - ny;
            p[3] = qz - nz;
            p[4] = qx;
            p[5] = qy;
            p[6] = qz;
            p[7] = nx;
            p[8] = ny;
            p[9] = nz;
            if (write_idx) out[feat_total + qlin * KK + t] = (float)j;
        }
    }
}

extern "C" void kernel_launch(void* const* d_in, const int* in_sizes, int n_in,
                              void* d_out, int out_size) {
    const float* xyz = (const float*)d_in[0];
    float* out = (float*)d_out;

    k_pre<<<BB + (BB * NC + 255) / 256, 256>>>(xyz);
    k_count<<<(BB * NN + 255) / 256, 256>>>(xyz);
    k_scan1<<<BB * NBLK, 256>>>();
    k_scan2<<<1, BB * 32>>>();
    k_scan3<<<BB * NBLK, 256>>>();
    k_scatter<<<(BB * NN + 255) / 256, 256>>>(xyz);
    k_search<<<(BB * NN / 2) / WPB, TPB>>>(xyz, out, out_size);
}